// round 16
// baseline (speedup 1.0000x reference)
#include <cuda_runtime.h>
#include <cuda_bf16.h>
#include <cstdint>

#define NU 100000          // users
#define NM 20000           // movies
#define NE 1000000         // edges per direction
#define NLOOP 20000        // self loops (min(NU,NM))
#define ET (NE + NLOOP)
#define HD 64

// ---------------- scratch (static device globals; zero at module load) ------
__device__ float g_suA[NU],  g_suB[NU];       // user segment sums (layer 0 / 1)
__device__ float g_accu[(size_t)NU * HD];     // user accumulator (re-zeroed by consumers)
__device__ float g_xlu[(size_t)NU * HD];   // user  src-proj (xl of u2m)
__device__ float g_xru[(size_t)NU * HD];   // user  dst-proj (xr of m2u)
__device__ float g_xlm[(size_t)NM * HD];   // movie src-proj (xl of m2u)
__device__ float g_xrm[(size_t)NM * HD];   // movie dst-proj (xr of u2m)
__device__ float g_xm[(size_t)NM * HD];    // layer-0 movie output (post-SELU)
__device__ int   g_cntm[NM];
__device__ int   g_offm[NM + 1];
__device__ int   g_curm[NM];
__device__ int   g_csrm[ET];               // user src indices, movie-dst-grouped

// ---------------- helpers ----------------------------------------------------
__device__ __forceinline__ float selu_f(float x)
{
    const float SCALE = 1.0507009873554805f;
    const float SA    = 1.7580993408473766f;   // scale * alpha
    return x > 0.f ? SCALE * x : SA * (__expf(x) - 1.f);
}

__device__ __forceinline__ void split_tf32(float x, uint32_t& hi, uint32_t& lo)
{
    uint32_t h;
    asm("cvt.rna.tf32.f32 %0, %1;" : "=r"(h) : "f"(x));
    float r = x - __uint_as_float(h);
    uint32_t l;
    asm("cvt.rna.tf32.f32 %0, %1;" : "=r"(l) : "f"(r));
    hi = h; lo = l;
}

__device__ __forceinline__ void mma_tf32(float c[4],
                                         uint32_t a0, uint32_t a1, uint32_t a2, uint32_t a3,
                                         uint32_t b0, uint32_t b1)
{
    asm volatile("mma.sync.aligned.m16n8k8.row.col.f32.tf32.tf32.f32 "
                 "{%0,%1,%2,%3}, {%4,%5,%6,%7}, {%8,%9}, {%0,%1,%2,%3};"
                 : "+f"(c[0]), "+f"(c[1]), "+f"(c[2]), "+f"(c[3])
                 : "r"(a0), "r"(a1), "r"(a2), "r"(a3), "r"(b0), "r"(b1));
}

// ---------------- movie CSR build (once per launch, reused by both layers) ---
__global__ void zero_k(int* __restrict__ p, int n)
{
    int i = blockIdx.x * blockDim.x + threadIdx.x;
    if (i < n) p[i] = 0;
}

__global__ void histm_k(const int* __restrict__ edst, int* __restrict__ cnt)
{
    int e = blockIdx.x * blockDim.x + threadIdx.x;
    if (e >= ET) return;
    int d = (e < NE) ? edst[e] : e - NE;
    atomicAdd(&cnt[d], 1);
}

__global__ void scanm_k(const int* __restrict__ cnt, int* __restrict__ off,
                        int* __restrict__ cur)
{
    __shared__ int part[1024];
    int t = threadIdx.x;
    const int n = NM;
    int chunk = (n + 1023) >> 10;
    int b = t * chunk;
    int e = min(b + chunk, n);
    int s = 0;
    for (int i = b; i < e; i++) s += cnt[i];
    part[t] = s;
    __syncthreads();
    for (int o = 1; o < 1024; o <<= 1) {
        int v = (t >= o) ? part[t - o] : 0;
        __syncthreads();
        part[t] += v;
        __syncthreads();
    }
    int run = (t == 0) ? 0 : part[t - 1];
    for (int i = b; i < e; i++) {
        off[i] = run; cur[i] = run;
        run += cnt[i];
    }
    if (t == 1023) off[n] = part[1023];
}

__global__ void reorderm_k(const int* __restrict__ esrc, const int* __restrict__ edst,
                           int* __restrict__ cur, int* __restrict__ csr)
{
    int e = blockIdx.x * blockDim.x + threadIdx.x;
    if (e >= ET) return;
    int s, d;
    if (e < NE) { s = esrc[e]; d = edst[e]; } else { s = e - NE; d = s; }
    int pos = atomicAdd(&cur[d], 1);
    csr[pos] = s;
}

// ---------------- tensor-core dual-side, dual-output GEMM --------------------
// blocks [0,GU): user rows; [GU,GU+GM): movie rows (R10-proven 3xTF32 body).
// fusedU=1: user X = selu(accu/suIn + biasU), read+re-zeroed in place.
// Movie X always comes from Xm (layer-0: input; layer-1: conv-gather output).
// Zeroes THIS layer's user segment sums (suZ) via grid-stride.
__global__ void gemm2_tc_k(const float* __restrict__ Xu, const float* __restrict__ Xm,
                           const float* __restrict__ W1u, const float* __restrict__ B1u,
                           const float* __restrict__ W2u, const float* __restrict__ B2u,
                           const float* __restrict__ W1m, const float* __restrict__ B1m,
                           const float* __restrict__ W2m, const float* __restrict__ B2m,
                           float* __restrict__ Y1u, float* __restrict__ Y2u,
                           float* __restrict__ Y1m, float* __restrict__ Y2m,
                           float* __restrict__ suZ,
                           int fusedU,
                           float* __restrict__ accU,
                           const float* __restrict__ suIn, const float* __restrict__ biasU,
                           int GU)
{
    for (int z = blockIdx.x * blockDim.x + threadIdx.x; z < NU;
         z += gridDim.x * blockDim.x) suZ[z] = 0.f;

    __shared__ float Xs[64][68];

    int tid = threadIdx.x;           // 256 threads
    int bid = blockIdx.x;

    const float *X, *B1, *B2, *W1, *W2;
    float *Y1, *Y2;
    int N, userSide;
    if (bid < GU) {
        X = Xu; W1 = W1u; B1 = B1u; W2 = W2u; B2 = B2u;
        Y1 = Y1u; Y2 = Y2u; N = NU; userSide = 1;
    } else {
        bid -= GU;
        X = Xm; W1 = W1m; B1 = B1m; W2 = W2m; B2 = B2m;
        Y1 = Y1m; Y2 = Y2m; N = NM; userSide = 0;
    }
    int rowblk = bid * 64;

#pragma unroll
    for (int i = 0; i < 4; i++) {
        int idx = tid + i * 256;     // float4 index over [64][16]
        int r = idx >> 4, c4 = idx & 15;
        int grow = rowblk + r;
        float4 v = make_float4(0.f, 0.f, 0.f, 0.f);
        if (grow < N) {
            if (userSide && fusedU) {
                float4 a = ((const float4*)accU)[(size_t)grow * 16 + c4];
                float inv = 1.f / (suIn[grow] + 1e-16f);
                float4 b = ((const float4*)biasU)[c4];
                v.x = selu_f(a.x * inv + b.x);
                v.y = selu_f(a.y * inv + b.y);
                v.z = selu_f(a.z * inv + b.z);
                v.w = selu_f(a.w * inv + b.w);
                ((float4*)accU)[(size_t)grow * 16 + c4] = make_float4(0.f, 0.f, 0.f, 0.f);
            } else {
                v = ((const float4*)X)[(size_t)grow * 16 + c4];
            }
        }
        *(float4*)&Xs[r][c4 * 4] = v;
    }
    __syncthreads();

    int wid  = tid >> 5;
    int lane = tid & 31;
    int warp_m = wid & 3;
    int warp_n = wid >> 2;
    const float* W  = warp_n ? W2 : W1;
    const float* Bv = warp_n ? B2 : B1;
    float*       Y  = warp_n ? Y2 : Y1;

    int row0 = warp_m * 16;
    int qid = lane >> 2;
    int rid = lane & 3;

    float c[8][4];
#pragma unroll
    for (int nt = 0; nt < 8; nt++)
#pragma unroll
        for (int j = 0; j < 4; j++) c[nt][j] = 0.f;

#pragma unroll
    for (int k0 = 0; k0 < 64; k0 += 8) {
        float fa0 = Xs[row0 + qid    ][k0 + rid    ];
        float fa1 = Xs[row0 + qid + 8][k0 + rid    ];
        float fa2 = Xs[row0 + qid    ][k0 + rid + 4];
        float fa3 = Xs[row0 + qid + 8][k0 + rid + 4];
        uint32_t ah0, al0, ah1, al1, ah2, al2, ah3, al3;
        split_tf32(fa0, ah0, al0);
        split_tf32(fa1, ah1, al1);
        split_tf32(fa2, ah2, al2);
        split_tf32(fa3, ah3, al3);

#pragma unroll
        for (int nt = 0; nt < 8; nt++) {
            int n = nt * 8 + qid;
            float fb0 = __ldg(&W[(k0 + rid    ) * 64 + n]);
            float fb1 = __ldg(&W[(k0 + rid + 4) * 64 + n]);
            uint32_t bh0, bl0, bh1, bl1;
            split_tf32(fb0, bh0, bl0);
            split_tf32(fb1, bh1, bl1);

            mma_tf32(c[nt], ah0, ah1, ah2, ah3, bh0, bh1);   // hi*hi
            mma_tf32(c[nt], ah0, ah1, ah2, ah3, bl0, bl1);   // hi*lo
            mma_tf32(c[nt], al0, al1, al2, al3, bh0, bh1);   // lo*hi
        }
    }

    int r0 = rowblk + row0 + qid;
    int r1 = r0 + 8;
#pragma unroll
    for (int nt = 0; nt < 8; nt++) {
        int cb = nt * 8 + rid * 2;
        float2 bv = *(const float2*)&Bv[cb];
        if (r0 < N) {
            float2 o; o.x = c[nt][0] + bv.x; o.y = c[nt][1] + bv.y;
            *(float2*)&Y[(size_t)r0 * 64 + cb] = o;
        }
        if (r1 < N) {
            float2 o; o.x = c[nt][2] + bv.x; o.y = c[nt][3] + bv.y;
            *(float2*)&Y[(size_t)r1 * 64 + cb] = o;
        }
    }
}

// ---------------- merged conv ------------------------------------------------
// blocks [0,CB): m2u scatter (R2 shape) -> accu + su atomics  (bandwidth-bound, FIRST)
// blocks [CB,CB+NM): block-per-movie u2m gather -> writes movie output directly
__global__ void conv_merged_k(const int* __restrict__ em,
                              const int* __restrict__ offm, const int* __restrict__ csrm,
                              const float* __restrict__ xlu, const float* __restrict__ xrm,
                              const float* __restrict__ xlm, const float* __restrict__ xru,
                              const float* __restrict__ att0, const float* __restrict__ bias0,
                              const float* __restrict__ att1,
                              float* __restrict__ outm,
                              float* __restrict__ su_, float* __restrict__ accu,
                              int CB)
{
    __shared__ float s_acc[16][64];
    __shared__ float s_sum[16];

    if (blockIdx.x < CB) {
        // ----- m2u scatter: one 16-lane group per edge -----------------------
        int t = blockIdx.x * blockDim.x + threadIdx.x;
        int g = t >> 4;
        if (g >= ET) return;
        int lane = t & 15;
        int s, d;
        if (g < NE) { s = em[g]; d = em[NE + g]; } else { s = g - NE; d = s; }

        float4 a = ((const float4*)xlm)[(size_t)s * 16 + lane];
        float4 b = ((const float4*)xru)[(size_t)d * 16 + lane];
        float4 w = ((const float4*)att1)[lane];

        float vx = a.x + b.x; vx = vx > 0.f ? vx : 0.2f * vx;
        float vy = a.y + b.y; vy = vy > 0.f ? vy : 0.2f * vy;
        float vz = a.z + b.z; vz = vz > 0.f ? vz : 0.2f * vz;
        float vw = a.w + b.w; vw = vw > 0.f ? vw : 0.2f * vw;
        float p = vx * w.x + vy * w.y + vz * w.z + vw * w.w;
#pragma unroll
        for (int o = 8; o > 0; o >>= 1) p += __shfl_xor_sync(0xffffffffu, p, o);
        float ex = __expf(p);

        if (lane == 0) atomicAdd(&su_[d], ex);

        a.x *= ex; a.y *= ex; a.z *= ex; a.w *= ex;
        float* pp = accu + (size_t)d * HD + lane * 4;
        asm volatile("red.global.add.v4.f32 [%0], {%1,%2,%3,%4};"
                     :: "l"(pp), "f"(a.x), "f"(a.y), "f"(a.z), "f"(a.w) : "memory");
    } else {
        // ----- block-per-movie gather: out[d] = selu(bias + Σex·xl / Σex) ----
        int d   = blockIdx.x - CB;
        int tid = threadIdx.x;           // 256
        int gid = tid >> 4;              // 16 groups of 16 lanes
        int l16 = tid & 15;

        int beg = offm[d], end = offm[d + 1];
        int iters = (end - beg + 15) >> 4;   // block-uniform trip count

        float4 xr4 = ((const float4*)xrm)[(size_t)d * 16 + l16];
        float4 w4  = ((const float4*)att0)[l16];

        float4 acc = make_float4(0.f, 0.f, 0.f, 0.f);
        float  sum = 0.f;

        for (int it = 0; it < iters; it++) {
            int idx = beg + it * 16 + gid;
            bool v = idx < end;
            int s = csrm[v ? idx : beg];
            float4 a = ((const float4*)xlu)[(size_t)s * 16 + l16];
            float vx = a.x + xr4.x; vx = vx > 0.f ? vx : 0.2f * vx;
            float vy = a.y + xr4.y; vy = vy > 0.f ? vy : 0.2f * vy;
            float vz = a.z + xr4.z; vz = vz > 0.f ? vz : 0.2f * vz;
            float vw = a.w + xr4.w; vw = vw > 0.f ? vw : 0.2f * vw;
            float p = vx * w4.x + vy * w4.y + vz * w4.z + vw * w4.w;
#pragma unroll
            for (int o = 8; o > 0; o >>= 1) p += __shfl_xor_sync(0xffffffffu, p, o);
            float ex = v ? __expf(p) : 0.f;
            sum   += ex;
            acc.x += ex * a.x; acc.y += ex * a.y;
            acc.z += ex * a.z; acc.w += ex * a.w;
        }

        s_acc[gid][l16 * 4 + 0] = acc.x;
        s_acc[gid][l16 * 4 + 1] = acc.y;
        s_acc[gid][l16 * 4 + 2] = acc.z;
        s_acc[gid][l16 * 4 + 3] = acc.w;
        if (l16 == 0) s_sum[gid] = sum;
        __syncthreads();

        if (tid < 64) {
            float a = 0.f, tot = 0.f;
#pragma unroll
            for (int g2 = 0; g2 < 16; g2++) { a += s_acc[g2][tid]; tot += s_sum[g2]; }
            outm[(size_t)d * HD + tid] = selu_f(a / (tot + 1e-16f) + bias0[tid]);
        }
    }
}

// ---------------- finalize users (float4) + re-zero accu ---------------------
__global__ void finalizeu_k(float* __restrict__ accu, const float* __restrict__ su_,
                            const float* __restrict__ bias, float* __restrict__ out)
{
    int i = blockIdx.x * blockDim.x + threadIdx.x;   // float4 index
    if (i >= NU * (HD / 4)) return;
    int row = i >> 4;
    int c4  = i & 15;
    float inv = 1.f / (su_[row] + 1e-16f);
    float4 a = ((const float4*)accu)[i];
    float4 b = ((const float4*)bias)[c4];
    float4 o;
    o.x = selu_f(a.x * inv + b.x);
    o.y = selu_f(a.y * inv + b.y);
    o.z = selu_f(a.z * inv + b.z);
    o.w = selu_f(a.w * inv + b.w);
    ((float4*)out)[i] = o;
    ((float4*)accu)[i] = make_float4(0.f, 0.f, 0.f, 0.f);   // for next replay
}

// ---------------- host ------------------------------------------------------
extern "C" void kernel_launch(void* const* d_in, const int* in_sizes, int n_in,
                              void* d_out, int out_size)
{
    const float* x_user  = (const float*)d_in[0];
    const float* x_movie = (const float*)d_in[1];
    const int*   e_u2m   = (const int*)d_in[2];
    const int*   e_m2u   = (const int*)d_in[3];
    const float* Wl      = (const float*)d_in[4];
    const float* bl      = (const float*)d_in[5];
    const float* Wr      = (const float*)d_in[6];
    const float* br      = (const float*)d_in[7];
    const float* att     = (const float*)d_in[8];
    const float* bias    = (const float*)d_in[9];
    float* out = (float*)d_out;

    float *suA, *suB, *accu, *xlu, *xru, *xlm, *xrm, *xm;
    int *cntm, *offm, *curm, *csrm;
    cudaGetSymbolAddress((void**)&suA,  g_suA);
    cudaGetSymbolAddress((void**)&suB,  g_suB);
    cudaGetSymbolAddress((void**)&accu, g_accu);
    cudaGetSymbolAddress((void**)&xlu,  g_xlu);
    cudaGetSymbolAddress((void**)&xru,  g_xru);
    cudaGetSymbolAddress((void**)&xlm,  g_xlm);
    cudaGetSymbolAddress((void**)&xrm,  g_xrm);
    cudaGetSymbolAddress((void**)&xm,   g_xm);
    cudaGetSymbolAddress((void**)&cntm, g_cntm);
    cudaGetSymbolAddress((void**)&offm, g_offm);
    cudaGetSymbolAddress((void**)&curm, g_curm);
    cudaGetSymbolAddress((void**)&csrm, g_csrm);

    const int EB  = (ET + 255) / 256;
    const int GU  = (NU + 63) / 64;
    const int GM  = (NM + 63) / 64;
    const int CB  = ((long)ET * 16 + 255) / 256;   // m2u scatter blocks
    const int FBU = (NU * (HD / 4) + 255) / 256;

    // ---- movie-side CSR (built once, reused by both layers) ----------------
    zero_k<<<(NM + 255) / 256, 256>>>(cntm, NM);
    histm_k<<<EB, 256>>>(e_u2m + NE, cntm);
    scanm_k<<<1, 1024>>>(cntm, offm, curm);
    reorderm_k<<<EB, 256>>>(e_u2m, e_u2m + NE, curm, csrm);

    // ---- layer 0 (p0=0 u2m, p1=1 m2u) --------------------------------------
    gemm2_tc_k<<<GU + GM, 256>>>(x_user, x_movie,
        Wl + 0 * 4096, bl + 0 * 64,     // user xl (u2m)
        Wr + 1 * 4096, br + 1 * 64,     // user xr (m2u)
        Wl + 1 * 4096, bl + 1 * 64,     // movie xl (m2u)
        Wr + 0 * 4096, br + 0 * 64,     // movie xr (u2m)
        xlu, xru, xlm, xrm, suA,
        /*fusedU=*/0, nullptr, nullptr, nullptr, GU);

    conv_merged_k<<<CB + NM, 256>>>(e_m2u, offm, csrm,
        xlu, xrm, xlm, xru,
        att + 0 * 64, bias + 0 * 64, att + 1 * 64,
        xm, suA, accu, CB);

    // ---- layer 1 (p0=2 u2m, p1=3 m2u); user finalize fused into GEMM -------
    gemm2_tc_k<<<GU + GM, 256>>>(nullptr, xm,
        Wl + 2 * 4096, bl + 2 * 64,
        Wr + 3 * 4096, br + 3 * 64,
        Wl + 3 * 4096, bl + 3 * 64,
        Wr + 2 * 4096, br + 2 * 64,
        xlu, xru, xlm, xrm, suB,
        /*fusedU=*/1, accu, suA, bias + 1 * 64, GU);

    conv_merged_k<<<CB + NM, 256>>>(e_m2u, offm, csrm,
        xlu, xrm, xlm, xru,
        att + 2 * 64, bias + 2 * 64, att + 3 * 64,
        out + (size_t)NU * HD, suB, accu, CB);

    finalizeu_k<<<FBU, 256>>>(accu, suB, bias + 3 * 64, out);
}

// round 17
// speedup vs baseline: 1.1390x; 1.1390x over previous
#include <cuda_runtime.h>
#include <cuda_fp16.h>
#include <cstdint>

#define NU 100000          // users
#define NM 20000           // movies
#define NE 1000000         // edges per direction
#define NLOOP 20000        // self loops (min(NU,NM))
#define ET (NE + NLOOP)
#define HD 64

// ---------------- scratch (static device globals; zero at module load) ------
__device__ float  g_smA[NM],  g_suA[NU];      // layer-0 segment sums
__device__ float  g_smB[NM],  g_suB[NU];      // layer-1 segment sums
__device__ float  g_accm[(size_t)NM * HD];    // re-zeroed by each consumer
__device__ float  g_accu[(size_t)NU * HD];
__device__ __half g_xlu[(size_t)NU * HD];  // user  src-proj (xl of u2m), fp16
__device__ __half g_xru[(size_t)NU * HD];  // user  dst-proj (xr of m2u), fp16
__device__ __half g_xlm[(size_t)NM * HD];  // movie src-proj (xl of m2u), fp16
__device__ __half g_xrm[(size_t)NM * HD];  // movie dst-proj (xr of u2m), fp16

// ---------------- helpers ----------------------------------------------------
__device__ __forceinline__ float selu_f(float x)
{
    const float SCALE = 1.0507009873554805f;
    const float SA    = 1.7580993408473766f;   // scale * alpha
    return x > 0.f ? SCALE * x : SA * (__expf(x) - 1.f);
}

__device__ __forceinline__ void split_tf32(float x, uint32_t& hi, uint32_t& lo)
{
    uint32_t h;
    asm("cvt.rna.tf32.f32 %0, %1;" : "=r"(h) : "f"(x));
    float r = x - __uint_as_float(h);
    uint32_t l;
    asm("cvt.rna.tf32.f32 %0, %1;" : "=r"(l) : "f"(r));
    hi = h; lo = l;
}

__device__ __forceinline__ void mma_tf32(float c[4],
                                         uint32_t a0, uint32_t a1, uint32_t a2, uint32_t a3,
                                         uint32_t b0, uint32_t b1)
{
    asm volatile("mma.sync.aligned.m16n8k8.row.col.f32.tf32.tf32.f32 "
                 "{%0,%1,%2,%3}, {%4,%5,%6,%7}, {%8,%9}, {%0,%1,%2,%3};"
                 : "+f"(c[0]), "+f"(c[1]), "+f"(c[2]), "+f"(c[3])
                 : "r"(a0), "r"(a1), "r"(a2), "r"(a3), "r"(b0), "r"(b1));
}

// ---------------- tensor-core dual-side, dual-output GEMM --------------------
// blocks [0,GU): user rows; [GU,GU+GM): movie rows (R10-proven 3xTF32 body).
// Outputs are written as fp16 (consumed only by the conv edge pass).
// fused=0: X from Xu/Xm. fused=1: X = selu(acc/segsum + bias_prev) from
// accU/accM (re-zeroed in place), using the PREVIOUS layer's segment sums.
// Always zeroes THIS layer's segment-sum pair (smZ/suZ) via grid-stride.
__global__ void gemm2_tc_k(const float* __restrict__ Xu, const float* __restrict__ Xm,
                           const float* __restrict__ W1u, const float* __restrict__ B1u,
                           const float* __restrict__ W2u, const float* __restrict__ B2u,
                           const float* __restrict__ W1m, const float* __restrict__ B1m,
                           const float* __restrict__ W2m, const float* __restrict__ B2m,
                           __half* __restrict__ Y1u, __half* __restrict__ Y2u,
                           __half* __restrict__ Y1m, __half* __restrict__ Y2m,
                           float* __restrict__ smZ, float* __restrict__ suZ,
                           int fused,
                           float* __restrict__ accU, float* __restrict__ accM,
                           const float* __restrict__ suIn, const float* __restrict__ smIn,
                           const float* __restrict__ biasU, const float* __restrict__ biasM,
                           int GU)
{
    // zero THIS layer's segment-sum buffers (their last consumer already ran)
    for (int z = blockIdx.x * blockDim.x + threadIdx.x; z < NM + NU;
         z += gridDim.x * blockDim.x) {
        if (z < NM) smZ[z] = 0.f; else suZ[z - NM] = 0.f;
    }

    __shared__ float Xs[64][68];     // stride 68: A-frag LDS is bank-conflict-free

    int tid = threadIdx.x;           // 256 threads
    int bid = blockIdx.x;

    const float *X, *B1, *B2, *W1, *W2;
    __half *Y1, *Y2;
    float *accX; const float *sIn, *biasP;
    int N;
    if (bid < GU) {
        X = Xu; W1 = W1u; B1 = B1u; W2 = W2u; B2 = B2u;
        Y1 = Y1u; Y2 = Y2u; N = NU;
        accX = accU; sIn = suIn; biasP = biasU;
    } else {
        bid -= GU;
        X = Xm; W1 = W1m; B1 = B1m; W2 = W2m; B2 = B2m;
        Y1 = Y1m; Y2 = Y2m; N = NM;
        accX = accM; sIn = smIn; biasP = biasM;
    }
    int rowblk = bid * 64;

    // fill Xs[64][64 used of 68]
#pragma unroll
    for (int i = 0; i < 4; i++) {
        int idx = tid + i * 256;     // float4 index over [64][16]
        int r = idx >> 4, c4 = idx & 15;
        int grow = rowblk + r;
        float4 v = make_float4(0.f, 0.f, 0.f, 0.f);
        if (grow < N) {
            if (!fused) {
                v = ((const float4*)X)[(size_t)grow * 16 + c4];
            } else {
                float4 a = ((const float4*)accX)[(size_t)grow * 16 + c4];
                float inv = 1.f / (sIn[grow] + 1e-16f);
                float4 b = ((const float4*)biasP)[c4];
                v.x = selu_f(a.x * inv + b.x);
                v.y = selu_f(a.y * inv + b.y);
                v.z = selu_f(a.z * inv + b.z);
                v.w = selu_f(a.w * inv + b.w);
                // re-zero acc in place for this layer's conv (exactly-once per elem)
                ((float4*)accX)[(size_t)grow * 16 + c4] = make_float4(0.f, 0.f, 0.f, 0.f);
            }
        }
        *(float4*)&Xs[r][c4 * 4] = v;
    }
    __syncthreads();

    int wid  = tid >> 5;
    int lane = tid & 31;
    int warp_m = wid & 3;            // row group of 16
    int warp_n = wid >> 2;           // 0 -> (W1,B1,Y1), 1 -> (W2,B2,Y2)
    const float* W  = warp_n ? W2 : W1;
    const float* Bv = warp_n ? B2 : B1;
    __half*      Y  = warp_n ? Y2 : Y1;

    int row0 = warp_m * 16;
    int qid = lane >> 2;             // t/4 : 0..7
    int rid = lane & 3;              // t%4 : 0..3

    float c[8][4];
#pragma unroll
    for (int nt = 0; nt < 8; nt++)
#pragma unroll
        for (int j = 0; j < 4; j++) c[nt][j] = 0.f;

#pragma unroll
    for (int k0 = 0; k0 < 64; k0 += 8) {
        // A fragment (m16 x k8), rows row0+qid / +8, cols k0+rid / +4
        float fa0 = Xs[row0 + qid    ][k0 + rid    ];
        float fa1 = Xs[row0 + qid + 8][k0 + rid    ];
        float fa2 = Xs[row0 + qid    ][k0 + rid + 4];
        float fa3 = Xs[row0 + qid + 8][k0 + rid + 4];
        uint32_t ah0, al0, ah1, al1, ah2, al2, ah3, al3;
        split_tf32(fa0, ah0, al0);
        split_tf32(fa1, ah1, al1);
        split_tf32(fa2, ah2, al2);
        split_tf32(fa3, ah3, al3);

#pragma unroll
        for (int nt = 0; nt < 8; nt++) {
            // B fragment (k8 x n8): b0 = W[k0+rid][n], b1 = W[k0+rid+4][n], n = nt*8+qid
            int n = nt * 8 + qid;
            float fb0 = __ldg(&W[(k0 + rid    ) * 64 + n]);
            float fb1 = __ldg(&W[(k0 + rid + 4) * 64 + n]);
            uint32_t bh0, bl0, bh1, bl1;
            split_tf32(fb0, bh0, bl0);
            split_tf32(fb1, bh1, bl1);

            mma_tf32(c[nt], ah0, ah1, ah2, ah3, bh0, bh1);   // hi*hi
            mma_tf32(c[nt], ah0, ah1, ah2, ah3, bl0, bl1);   // hi*lo
            mma_tf32(c[nt], al0, al1, al2, al3, bh0, bh1);   // lo*hi
        }
    }

    // epilogue: + bias, convert to fp16, store half2 pairs
    int r0 = rowblk + row0 + qid;
    int r1 = r0 + 8;
#pragma unroll
    for (int nt = 0; nt < 8; nt++) {
        int cb = nt * 8 + rid * 2;
        float2 bv = *(const float2*)&Bv[cb];
        if (r0 < N) {
            __half2 h = __floats2half2_rn(c[nt][0] + bv.x, c[nt][1] + bv.y);
            *(__half2*)&Y[(size_t)r0 * 64 + cb] = h;
        }
        if (r1 < N) {
            __half2 h = __floats2half2_rn(c[nt][2] + bv.x, c[nt][3] + bv.y);
            *(__half2*)&Y[(size_t)r1 * 64 + cb] = h;
        }
    }
}

// ---------------- fused edge pass, both directions in one launch -------------
// xl/xr are fp16 rows (128 B each); math in fp32; acc stays fp32 red.v4.
__global__ void conv_dual_k(const int* __restrict__ eu, const int* __restrict__ em,
                            const __half* __restrict__ xlu, const __half* __restrict__ xrm,
                            const __half* __restrict__ xlm, const __half* __restrict__ xru,
                            const float* __restrict__ att0, const float* __restrict__ att1,
                            float* __restrict__ sm_, float* __restrict__ su_,
                            float* __restrict__ accm, float* __restrict__ accu,
                            int CB)
{
    const int *esrc, *edst;
    const __half *xl, *xr;
    const float *att;
    float *sbuf, *acc;
    int bid = blockIdx.x;
    if (bid < CB) {
        esrc = eu; edst = eu + NE; xl = xlu; xr = xrm; att = att0;
        sbuf = sm_; acc = accm;
    } else {
        bid -= CB;
        esrc = em; edst = em + NE; xl = xlm; xr = xru; att = att1;
        sbuf = su_; acc = accu;
    }

    int t = bid * blockDim.x + threadIdx.x;
    int g = t >> 4;
    if (g >= ET) return;
    int lane = t & 15;
    int s, d;
    if (g < NE) { s = esrc[g]; d = edst[g]; } else { s = g - NE; d = s; }

    // 4 dims per lane: 4 halves = 8 bytes (uint2)
    uint2 ra = ((const uint2*)xl)[(size_t)s * 16 + lane];
    uint2 rb = ((const uint2*)xr)[(size_t)d * 16 + lane];
    float2 a01 = __half22float2(*(__half2*)&ra.x);
    float2 a23 = __half22float2(*(__half2*)&ra.y);
    float2 b01 = __half22float2(*(__half2*)&rb.x);
    float2 b23 = __half22float2(*(__half2*)&rb.y);
    float4 a = make_float4(a01.x, a01.y, a23.x, a23.y);
    float4 b = make_float4(b01.x, b01.y, b23.x, b23.y);
    float4 w = ((const float4*)att)[lane];

    float vx = a.x + b.x; vx = vx > 0.f ? vx : 0.2f * vx;
    float vy = a.y + b.y; vy = vy > 0.f ? vy : 0.2f * vy;
    float vz = a.z + b.z; vz = vz > 0.f ? vz : 0.2f * vz;
    float vw = a.w + b.w; vw = vw > 0.f ? vw : 0.2f * vw;
    float p = vx * w.x + vy * w.y + vz * w.z + vw * w.w;
#pragma unroll
    for (int o = 8; o > 0; o >>= 1) p += __shfl_xor_sync(0xffffffffu, p, o);
    float ex = __expf(p);

    if (lane == 0) atomicAdd(&sbuf[d], ex);

    a.x *= ex; a.y *= ex; a.z *= ex; a.w *= ex;
    float* pp = acc + (size_t)d * HD + lane * 4;
    asm volatile("red.global.add.v4.f32 [%0], {%1,%2,%3,%4};"
                 :: "l"(pp), "f"(a.x), "f"(a.y), "f"(a.z), "f"(a.w) : "memory");
}

// ---------------- finalize (float4) + re-zero acc (final layer only) ---------
__global__ void finalize2_k(float* __restrict__ accm, const float* __restrict__ sm_,
                            const float* __restrict__ bias0, float* __restrict__ outm,
                            float* __restrict__ accu, const float* __restrict__ su_,
                            const float* __restrict__ bias1, float* __restrict__ outu)
{
    int i = blockIdx.x * blockDim.x + threadIdx.x;   // float4 index
    const int NM4 = NM * (HD / 4);
    const int NT4 = (NM + NU) * (HD / 4);
    if (i >= NT4) return;

    float* acc; const float* sbuf; const float* bias; float* out; int j;
    if (i < NM4) { acc = accm; sbuf = sm_; bias = bias0; out = outm; j = i; }
    else         { acc = accu; sbuf = su_; bias = bias1; out = outu; j = i - NM4; }

    int row = j >> 4;
    int c4  = j & 15;
    float inv = 1.f / (sbuf[row] + 1e-16f);
    float4 a = ((const float4*)acc)[j];
    float4 b = ((const float4*)bias)[c4];

    float4 o;
    o.x = selu_f(a.x * inv + b.x);
    o.y = selu_f(a.y * inv + b.y);
    o.z = selu_f(a.z * inv + b.z);
    o.w = selu_f(a.w * inv + b.w);

    ((float4*)out)[j] = o;
    ((float4*)acc)[j] = make_float4(0.f, 0.f, 0.f, 0.f);   // re-zero for next replay
}

// ---------------- host ------------------------------------------------------
extern "C" void kernel_launch(void* const* d_in, const int* in_sizes, int n_in,
                              void* d_out, int out_size)
{
    const float* x_user  = (const float*)d_in[0];
    const float* x_movie = (const float*)d_in[1];
    const int*   e_u2m   = (const int*)d_in[2];
    const int*   e_m2u   = (const int*)d_in[3];
    const float* Wl      = (const float*)d_in[4];
    const float* bl      = (const float*)d_in[5];
    const float* Wr      = (const float*)d_in[6];
    const float* br      = (const float*)d_in[7];
    const float* att     = (const float*)d_in[8];
    const float* bias    = (const float*)d_in[9];
    float* out = (float*)d_out;

    float *smA, *suA, *smB, *suB, *accm, *accu;
    __half *xlu, *xru, *xlm, *xrm;
    cudaGetSymbolAddress((void**)&smA,  g_smA);
    cudaGetSymbolAddress((void**)&suA,  g_suA);
    cudaGetSymbolAddress((void**)&smB,  g_smB);
    cudaGetSymbolAddress((void**)&suB,  g_suB);
    cudaGetSymbolAddress((void**)&accm, g_accm);
    cudaGetSymbolAddress((void**)&accu, g_accu);
    cudaGetSymbolAddress((void**)&xlu,  g_xlu);
    cudaGetSymbolAddress((void**)&xru,  g_xru);
    cudaGetSymbolAddress((void**)&xlm,  g_xlm);
    cudaGetSymbolAddress((void**)&xrm,  g_xrm);

    const int GU  = (NU + 63) / 64;               // 1563 user gemm blocks
    const int GM  = (NM + 63) / 64;               // 313 movie gemm blocks
    const int CB  = ((long)ET * 16 + 255) / 256;  // 63750 conv blocks per direction
    const int FB4 = ((NM + NU) * (HD / 4) + 255) / 256;

    // ---- layer 0 (p0 = 0 u2m, p1 = 1 m2u) ----------------------------------
    gemm2_tc_k<<<GU + GM, 256>>>(x_user, x_movie,
        Wl + 0 * 4096, bl + 0 * 64,     // user xl (u2m)
        Wr + 1 * 4096, br + 1 * 64,     // user xr (m2u)
        Wl + 1 * 4096, bl + 1 * 64,     // movie xl (m2u)
        Wr + 0 * 4096, br + 0 * 64,     // movie xr (u2m)
        xlu, xru, xlm, xrm, smA, suA,
        /*fused=*/0, nullptr, nullptr, nullptr, nullptr, nullptr, nullptr, GU);

    conv_dual_k<<<2 * CB, 256>>>(e_u2m, e_m2u, xlu, xrm, xlm, xru,
        att + 0 * 64, att + 1 * 64, smA, suA, accm, accu, CB);

    // ---- layer 1 (p0 = 2, p1 = 3); layer-0 finalize fused into GEMM X load --
    gemm2_tc_k<<<GU + GM, 256>>>(nullptr, nullptr,
        Wl + 2 * 4096, bl + 2 * 64,
        Wr + 3 * 4096, br + 3 * 64,
        Wl + 3 * 4096, bl + 3 * 64,
        Wr + 2 * 4096, br + 2 * 64,
        xlu, xru, xlm, xrm, smB, suB,
        /*fused=*/1, accu, accm, suA, smA,
        bias + 1 * 64 /*user bias l0*/, bias + 0 * 64 /*movie bias l0*/, GU);

    conv_dual_k<<<2 * CB, 256>>>(e_u2m, e_m2u, xlu, xrm, xlm, xru,
        att + 2 * 64, att + 3 * 64, smB, suB, accm, accu, CB);

    finalize2_k<<<FB4, 256>>>(accm, smB, bias + 2 * 64, out + (size_t)NU * HD,
                              accu, suB, bias + 3 * 64, out);
}